// round 2
// baseline (speedup 1.0000x reference)
#include <cuda_runtime.h>
#include <cuda_fp16.h>
#include <math.h>

// Problem constants
#define Gn   64
#define Cn   32
#define Ln   128
#define Dn   64
#define Hn   128
#define NG   512          // 4*H gate width
#define NCLSn 10
#define BT   16           // sequences per CTA
#define NBATCH (Gn*Cn)    // 2048
#define NCTA (NBATCH/BT)  // 128
#define NTHR 512

// scratch: per-sequence summed hidden state [2048][128]
__device__ float g_rep[NBATCH * Hn];

// Shared memory layout (bytes)
#define SM_WIH 0                          // half [64][512]  = 65536
#define SM_WHH (SM_WIH + 64*512*2)        // half [128][512] = 131072
#define SM_XS  (SM_WHH + 128*512*2)       // float[64][16]   = 4096
#define SM_HS  (SM_XS + 64*16*4)          // float[128][16]  = 8192
#define SM_IB  (SM_HS + 128*16*4)         // float[16][128]  = 8192
#define SM_FB  (SM_IB + 16*128*4)         // float[16][128]  = 8192
#define SM_TOTAL (SM_FB + 16*128*4)       // 225280 bytes

__device__ __forceinline__ float sigf(float x) { return 1.0f / (1.0f + __expf(-x)); }

// 16 fp32 FMAs against a broadcast smem row of 16 floats
#define FMA16(ACC, PTR, W) do {                                          \
    const float4* _r = (const float4*)(PTR);                             \
    float4 _v0 = _r[0], _v1 = _r[1], _v2 = _r[2], _v3 = _r[3];           \
    ACC[0]  += _v0.x*(W); ACC[1]  += _v0.y*(W);                          \
    ACC[2]  += _v0.z*(W); ACC[3]  += _v0.w*(W);                          \
    ACC[4]  += _v1.x*(W); ACC[5]  += _v1.y*(W);                          \
    ACC[6]  += _v1.z*(W); ACC[7]  += _v1.w*(W);                          \
    ACC[8]  += _v2.x*(W); ACC[9]  += _v2.y*(W);                          \
    ACC[10] += _v2.z*(W); ACC[11] += _v2.w*(W);                          \
    ACC[12] += _v3.x*(W); ACC[13] += _v3.y*(W);                          \
    ACC[14] += _v3.z*(W); ACC[15] += _v3.w*(W);                          \
} while (0)

extern "C" __global__ void __launch_bounds__(NTHR, 1)
lstm_kernel(const float* __restrict__ x,    // [2048][128][64]
            const float* __restrict__ Wih,  // [512][64]
            const float* __restrict__ Whh,  // [512][128]
            const float* __restrict__ bih,  // [512]
            const float* __restrict__ bhh)  // [512]
{
    extern __shared__ unsigned char smem[];
    __half* WIH  = (__half*)(smem + SM_WIH);   // [d][n] transposed, fp16
    __half* WHH  = (__half*)(smem + SM_WHH);   // [k][n] transposed, fp16
    float*  xs   = (float*)(smem + SM_XS);     // [d][b]
    float*  hs   = (float*)(smem + SM_HS);     // [k][b]
    float*  ibuf = (float*)(smem + SM_IB);     // [b][j]  (i, then i*g)
    float*  fbuf = (float*)(smem + SM_FB);     // [b][j]

    const int tid  = threadIdx.x;
    const int n    = tid;          // gate-output column this thread owns
    const int gate = tid >> 7;     // 0=i, 1=f, 2=g, 3=o
    const int j    = tid & 127;    // hidden index within gate
    const int b0   = blockIdx.x * BT;

    // Stage weights transposed into smem as fp16 (one-time)
    for (int i = tid; i < NG * Dn; i += NTHR) {
        int nn = i >> 6, dd = i & 63;
        WIH[dd * NG + nn] = __float2half(Wih[i]);
    }
    for (int i = tid; i < NG * Hn; i += NTHR) {
        int nn = i >> 7, kk = i & 127;
        WHH[kk * NG + nn] = __float2half(Whh[i]);
    }
    for (int i = tid; i < Hn * BT; i += NTHR) hs[i] = 0.0f;

    const float bias = bih[n] + bhh[n];

    float c[BT], hsum[BT], tv[BT];
    #pragma unroll
    for (int b = 0; b < BT; b++) { c[b] = 0.0f; hsum[b] = 0.0f; }

    __syncthreads();

    for (int t = 0; t < Ln; t++) {
        // Stage x_t for this CTA's 16 sequences as xs[d][b]
        for (int i = tid; i < BT * Dn; i += NTHR) {
            int b = i >> 6, d = i & 63;
            xs[d * BT + b] = x[((size_t)(b0 + b) * Ln + t) * Dn + d];
        }
        __syncthreads();  // S1: xs ready; previous step's hs writes drained

        // Gate pre-activations for this thread's column n, all 16 sequences
        float acc[BT];
        #pragma unroll
        for (int b = 0; b < BT; b++) acc[b] = bias;

        #pragma unroll 4
        for (int d = 0; d < Dn; d++) {
            float w = __half2float(WIH[d * NG + n]);
            FMA16(acc, xs + d * BT, w);
        }
        #pragma unroll 4
        for (int k = 0; k < Hn; k++) {
            float w = __half2float(WHH[k * NG + n]);
            FMA16(acc, hs + k * BT, w);
        }

        // Activations; i/f go to smem, g/o stay in registers
        if (gate == 0) {
            #pragma unroll
            for (int b = 0; b < BT; b++) ibuf[b * Hn + j] = sigf(acc[b]);
        } else if (gate == 1) {
            #pragma unroll
            for (int b = 0; b < BT; b++) fbuf[b * Hn + j] = sigf(acc[b]);
        } else if (gate == 2) {
            #pragma unroll
            for (int b = 0; b < BT; b++) tv[b] = tanhf(acc[b]);
        } else {
            #pragma unroll
            for (int b = 0; b < BT; b++) tv[b] = sigf(acc[b]);
        }
        __syncthreads();  // S2: i,f visible

        if (gate == 2) {  // ibuf <- i * g
            #pragma unroll
            for (int b = 0; b < BT; b++) ibuf[b * Hn + j] *= tv[b];
        }
        __syncthreads();  // S3: i*g visible

        if (gate == 3) {  // o-threads own c, h, hsum
            #pragma unroll
            for (int b = 0; b < BT; b++) {
                c[b] = fbuf[b * Hn + j] * c[b] + ibuf[b * Hn + j];
                float hv = tv[b] * tanhf(c[b]);
                hsum[b] += hv;
                hs[j * BT + b] = hv;   // for next step's preacts
            }
        }
        // next-iteration S1 separates hs writes from hs reads
    }

    if (gate == 3) {
        #pragma unroll
        for (int b = 0; b < BT; b++)
            g_rep[(size_t)(b0 + b) * Hn + j] = hsum[b];
    }
}

// Mean over cycles + classifier + log_softmax. One CTA per graph.
extern "C" __global__ void head_kernel(const float* __restrict__ Wcls,  // [10][128]
                                       const float* __restrict__ bcls,  // [10]
                                       float* __restrict__ out)         // [64][10]
{
    __shared__ float gm[Hn];
    __shared__ float lg[NCLSn];
    const int g = blockIdx.x, tid = threadIdx.x;

    float s = 0.0f;
    for (int cc = 0; cc < Cn; cc++)
        s += g_rep[(size_t)(g * Cn + cc) * Hn + tid];
    gm[tid] = s * (1.0f / (float)Cn);
    __syncthreads();

    if (tid < NCLSn) {
        float a = bcls[tid];
        #pragma unroll 4
        for (int k = 0; k < Hn; k++) a += gm[k] * Wcls[tid * Hn + k];
        lg[tid] = a;
    }
    __syncthreads();

    if (tid == 0) {
        float m = lg[0];
        for (int i = 1; i < NCLSn; i++) m = fmaxf(m, lg[i]);
        float se = 0.0f;
        for (int i = 0; i < NCLSn; i++) se += expf(lg[i] - m);
        float lse = m + logf(se);
        for (int i = 0; i < NCLSn; i++) out[g * NCLSn + i] = lg[i] - lse;
    }
}

extern "C" void kernel_launch(void* const* d_in, const int* in_sizes, int n_in,
                              void* d_out, int out_size)
{
    const float* x    = (const float*)d_in[0];  // cycle_reps [64][32][128][64]
    const float* Wih  = (const float*)d_in[1];  // [512][64]
    const float* Whh  = (const float*)d_in[2];  // [512][128]
    const float* bih  = (const float*)d_in[3];  // [512]
    const float* bhh  = (const float*)d_in[4];  // [512]
    const float* Wcls = (const float*)d_in[5];  // [10][128]
    const float* bcls = (const float*)d_in[6];  // [10]
    float* out = (float*)d_out;

    cudaFuncSetAttribute(lstm_kernel,
                         cudaFuncAttributeMaxDynamicSharedMemorySize, SM_TOTAL);

    lstm_kernel<<<NCTA, NTHR, SM_TOTAL>>>(x, Wih, Whh, bih, bhh);
    head_kernel<<<Gn, Hn>>>(Wcls, bcls, out);
}

// round 3
// speedup vs baseline: 1.1115x; 1.1115x over previous
#include <cuda_runtime.h>
#include <cuda_fp16.h>
#include <math.h>

// Problem constants
#define Gn   64
#define Cn   32
#define Ln   128
#define Dn   64
#define Hn   128
#define NG   512          // 4*H gate width
#define NCLSn 10
#define BT   16           // sequences per CTA
#define NBATCH (Gn*Cn)    // 2048
#define NCTA (NBATCH/BT)  // 128
#define NTHR 512

// scratch: per-sequence summed hidden state [2048][128]
__device__ float g_rep[NBATCH * Hn];

// Shared memory layout (bytes)
#define SM_WIH 0                          // half [64][512]  = 65536
#define SM_WHH (SM_WIH + 64*512*2)        // half [128][512] = 131072
#define SM_XS  (SM_WHH + 128*512*2)       // float[64][16]   = 4096
#define SM_HS  (SM_XS + 64*16*4)          // float[128][16]  = 8192
#define SM_IB  (SM_HS + 128*16*4)         // float[16][128]  = 8192
#define SM_FB  (SM_IB + 16*128*4)         // float[16][128]  = 8192
#define SM_TOTAL (SM_FB + 16*128*4)       // 225280 bytes

__device__ __forceinline__ float tanh_ap(float x) {
    float y;
    asm("tanh.approx.f32 %0, %1;" : "=f"(y) : "f"(x));
    return y;
}
// fast sigmoid via HW tanh: sigma(x) = 0.5*tanh(x/2)+0.5
__device__ __forceinline__ float sig_fast(float x) {
    return fmaf(0.5f, tanh_ap(0.5f * x), 0.5f);
}
// accurate sigmoid (for f gate — errors compound through c recurrence)
__device__ __forceinline__ float sig_acc(float x) {
    return 1.0f / (1.0f + __expf(-x));
}

__device__ __forceinline__ unsigned long long pack2(float w) {
    unsigned long long r;
    asm("mov.b64 %0, {%1, %1};" : "=l"(r) : "f"(w));
    return r;
}
#define FMA2(acc, v, w2) \
    asm("fma.rn.f32x2 %0, %1, %2, %3;" : "=l"(acc) : "l"(v), "l"(w2), "l"(acc))
#define UNPK(lo, hi, v) \
    asm("mov.b64 {%0, %1}, %2;" : "=f"(lo), "=f"(hi) : "l"(v))

// 16 fp32 FMAs (as 8 packed f32x2) against a broadcast smem row of 16 floats
#define FMA16P(ACC, PTR, W2) do {                                        \
    const ulonglong2* _r = (const ulonglong2*)(PTR);                     \
    ulonglong2 _p0 = _r[0], _p1 = _r[1], _p2 = _r[2], _p3 = _r[3];       \
    FMA2(ACC[0], _p0.x, W2); FMA2(ACC[1], _p0.y, W2);                    \
    FMA2(ACC[2], _p1.x, W2); FMA2(ACC[3], _p1.y, W2);                    \
    FMA2(ACC[4], _p2.x, W2); FMA2(ACC[5], _p2.y, W2);                    \
    FMA2(ACC[6], _p3.x, W2); FMA2(ACC[7], _p3.y, W2);                    \
} while (0)

extern "C" __global__ void __launch_bounds__(NTHR, 1)
lstm_kernel(const float* __restrict__ x,    // [2048][128][64]
            const float* __restrict__ Wih,  // [512][64]
            const float* __restrict__ Whh,  // [512][128]
            const float* __restrict__ bih,  // [512]
            const float* __restrict__ bhh)  // [512]
{
    extern __shared__ unsigned char smem[];
    __half* WIH  = (__half*)(smem + SM_WIH);   // [d][n] transposed, fp16
    __half* WHH  = (__half*)(smem + SM_WHH);   // [k][n] transposed, fp16
    float*  xs   = (float*)(smem + SM_XS);     // [d][b]
    float*  hs   = (float*)(smem + SM_HS);     // [k][b]
    float*  ibuf = (float*)(smem + SM_IB);     // [b][j]  (i, then i*g)
    float*  fbuf = (float*)(smem + SM_FB);     // [b][j]

    const int tid  = threadIdx.x;
    const int n    = tid;          // gate-output column this thread owns
    const int gate = tid >> 7;     // 0=i, 1=f, 2=g, 3=o
    const int j    = tid & 127;    // hidden index within gate
    const int b0   = blockIdx.x * BT;

    // Stage weights transposed into smem as fp16 (one-time)
    for (int i = tid; i < NG * Dn; i += NTHR) {
        int nn = i >> 6, dd = i & 63;
        WIH[dd * NG + nn] = __float2half(Wih[i]);
    }
    for (int i = tid; i < NG * Hn; i += NTHR) {
        int nn = i >> 7, kk = i & 127;
        WHH[kk * NG + nn] = __float2half(Whh[i]);
    }
    for (int i = tid; i < Hn * BT; i += NTHR) hs[i] = 0.0f;

    const float bias = bih[n] + bhh[n];

    float c[BT], hsum[BT], tv[BT];
    #pragma unroll
    for (int b = 0; b < BT; b++) { c[b] = 0.0f; hsum[b] = 0.0f; }

    // x prefetch mapping: each thread stages 2 elements per step
    const int pb0 = tid >> 6;            // 0..7
    const int pd  = tid & 63;
    const int pb1 = (tid + NTHR) >> 6;   // 8..15
    const float* xb0 = x + ((size_t)(b0 + pb0) * Ln) * Dn + pd;
    const float* xb1 = x + ((size_t)(b0 + pb1) * Ln) * Dn + pd;
    float px0 = xb0[0];
    float px1 = xb1[0];

    __syncthreads();   // weights + hs init visible

    #pragma unroll 1
    for (int t = 0; t < Ln; t++) {
        // publish prefetched x_t as xs[d][b]
        xs[pd * BT + pb0] = px0;
        xs[pd * BT + pb1] = px1;
        __syncthreads();  // S1: xs ready; previous step's hs writes drained

        // prefetch x_{t+1}; LDG latency hidden behind the FMA loop
        if (t + 1 < Ln) {
            px0 = xb0[(t + 1) * Dn];
            px1 = xb1[(t + 1) * Dn];
        }

        // Gate pre-activations for this thread's column n, all 16 sequences
        unsigned long long acc[8];
        {
            unsigned long long b2 = pack2(bias);
            #pragma unroll
            for (int p = 0; p < 8; p++) acc[p] = b2;
        }

        #pragma unroll 4
        for (int d = 0; d < Dn; d++) {
            unsigned long long w2 = pack2(__half2float(WIH[d * NG + n]));
            FMA16P(acc, xs + d * BT, w2);
        }
        #pragma unroll 4
        for (int k = 0; k < Hn; k++) {
            unsigned long long w2 = pack2(__half2float(WHH[k * NG + n]));
            FMA16P(acc, hs + k * BT, w2);
        }

        float af[BT];
        #pragma unroll
        for (int p = 0; p < 8; p++) UNPK(af[2 * p], af[2 * p + 1], acc[p]);

        // Activations; i/f go to smem, g/o stay in registers
        if (gate == 0) {
            #pragma unroll
            for (int b = 0; b < BT; b++) ibuf[b * Hn + j] = sig_fast(af[b]);
        } else if (gate == 1) {
            #pragma unroll
            for (int b = 0; b < BT; b++) fbuf[b * Hn + j] = sig_acc(af[b]);
        } else if (gate == 2) {
            #pragma unroll
            for (int b = 0; b < BT; b++) tv[b] = tanh_ap(af[b]);
        } else {
            #pragma unroll
            for (int b = 0; b < BT; b++) tv[b] = sig_fast(af[b]);
        }
        __syncthreads();  // S2: i,f visible

        if (gate == 2) {  // ibuf <- i * g
            #pragma unroll
            for (int b = 0; b < BT; b++) ibuf[b * Hn + j] *= tv[b];
        }
        __syncthreads();  // S3: i*g visible

        if (gate == 3) {  // o-threads own c, h, hsum
            #pragma unroll
            for (int b = 0; b < BT; b++) {
                c[b] = fbuf[b * Hn + j] * c[b] + ibuf[b * Hn + j];
                float hv = tv[b] * tanh_ap(c[b]);
                hsum[b] += hv;
                hs[j * BT + b] = hv;   // for next step's preacts
            }
        }
        // next-iteration S1 separates hs writes from hs reads
    }

    if (gate == 3) {
        #pragma unroll
        for (int b = 0; b < BT; b++)
            g_rep[(size_t)(b0 + b) * Hn + j] = hsum[b];
    }
}

// Mean over cycles + classifier + log_softmax.
extern "C" __global__ void head_kernel(const float* __restrict__ Wcls,  // [10][128]
                                       const float* __restrict__ bcls,  // [10]
                                       float* __restrict__ out)         // [64][10]
{
    __shared__ float gm[Hn];
    __shared__ float lg[NCLSn];
    const int g = blockIdx.x, tid = threadIdx.x;

    float s = 0.0f;
    for (int cc = 0; cc < Cn; cc++)
        s += g_rep[(size_t)(g * Cn + cc) * Hn + tid];
    gm[tid] = s * (1.0f / (float)Cn);
    __syncthreads();

    if (tid < NCLSn) {
        float a = bcls[tid];
        #pragma unroll 4
        for (int k = 0; k < Hn; k++) a += gm[k] * Wcls[tid * Hn + k];
        lg[tid] = a;
    }
    __syncthreads();

    if (tid == 0) {
        float m = lg[0];
        for (int i = 1; i < NCLSn; i++) m = fmaxf(m, lg[i]);
        float se = 0.0f;
        for (int i = 0; i < NCLSn; i++) se += expf(lg[i] - m);
        float lse = m + logf(se);
        for (int i = 0; i < NCLSn; i++) out[g * NCLSn + i] = lg[i] - lse;
    }
}

extern "C" void kernel_launch(void* const* d_in, const int* in_sizes, int n_in,
                              void* d_out, int out_size)
{
    const float* x    = (const float*)d_in[0];  // cycle_reps [64][32][128][64]
    const float* Wih  = (const float*)d_in[1];  // [512][64]
    const float* Whh  = (const float*)d_in[2];  // [512][128]
    const float* bih  = (const float*)d_in[3];  // [512]
    const float* bhh  = (const float*)d_in[4];  // [512]
    const float* Wcls = (const float*)d_in[5];  // [10][128]
    const float* bcls = (const float*)d_in[6];  // [10]
    float* out = (float*)d_out;

    cudaFuncSetAttribute(lstm_kernel,
                         cudaFuncAttributeMaxDynamicSharedMemorySize, SM_TOTAL);

    lstm_kernel<<<NCTA, NTHR, SM_TOTAL>>>(x, Wih, Whh, bih, bhh);
    head_kernel<<<Gn, Hn>>>(Wcls, bcls, out);
}

// round 8
// speedup vs baseline: 5.8674x; 5.2788x over previous
#include <cuda_runtime.h>
#include <cuda_fp16.h>
#include <cstdint>
#include <math.h>

// ---------------- problem constants ----------------
#define Gn   64
#define Cn   32
#define Ln   128
#define Dn   64
#define Hn   128
#define NG   512          // 4*H gate rows
#define NCLSn 10
#define BT   16           // sequences per CTA
#define NBATCH (Gn*Cn)    // 2048
#define NCTA (NBATCH/BT)  // 128
#define NTHR 512

__device__ float g_rep[NBATCH * Hn];

// ---------------- smem layout (bytes) ----------------
// W   : fp16 [512 r][192 k], 3 chunks of [512][64], 128B rows, SW128 swizzle
// ACT : fp16 [16 b][192 k], 3 chunks of [16][64], 128B rows, SW128 swizzle
// PRE : fp16 [512 r][16 b], row stride 48B (padded, conflict-free)
#define SM_W     0                          // 3*512*128 = 196608
#define SM_ACT   196608                     // 3*16*128  = 6144
#define SM_PRE   (196608 + 6144)            // 512*48    = 24576
#define PRE_STR  48
#define SM_TOTAL (SM_PRE + NG*PRE_STR)      // 227328

// ---------------- helpers ----------------
__device__ __forceinline__ uint32_t smem_u32(const void* p) {
    uint32_t a;
    asm("{ .reg .u64 t; cvta.to.shared.u64 t, %1; cvt.u32.u64 %0, t; }" : "=r"(a) : "l"(p));
    return a;
}
__device__ __forceinline__ uint32_t swz(uint32_t o) { return o ^ ((o >> 3) & 0x70); }
// W chunked layout byte offset for (row n, k)
__device__ __forceinline__ uint32_t w_off(int n, int k) {
    return (uint32_t)((k >> 6) * 65536) + swz((uint32_t)(n * 128 + (k & 63) * 2));
}
// ACT chunked layout byte offset for (row b, k)
__device__ __forceinline__ uint32_t b_off(int b, int k) {
    return (uint32_t)((k >> 6) * 2048) + swz((uint32_t)(b * 128 + (k & 63) * 2));
}

#define LDSM4(R, A)                                                            \
    asm volatile("ldmatrix.sync.aligned.m8n8.x4.shared.b16 {%0,%1,%2,%3}, [%4];" \
        : "=r"((R)[0]), "=r"((R)[1]), "=r"((R)[2]), "=r"((R)[3]) : "r"(A))

#define MMA4(D, A, B0, B1)                                                     \
    asm volatile("mma.sync.aligned.m16n8k16.row.col.f32.f16.f16.f32 "          \
        "{%0,%1,%2,%3},{%4,%5,%6,%7},{%8,%9},{%0,%1,%2,%3};"                   \
        : "+f"((D)[0]), "+f"((D)[1]), "+f"((D)[2]), "+f"((D)[3])               \
        : "r"((A)[0]), "r"((A)[1]), "r"((A)[2]), "r"((A)[3]), "r"(B0), "r"(B1))

__device__ __forceinline__ float tanh_ap(float x) {
    float y; asm("tanh.approx.f32 %0, %1;" : "=f"(y) : "f"(x)); return y;
}
__device__ __forceinline__ float sig_fast(float x) { return fmaf(0.5f, tanh_ap(0.5f * x), 0.5f); }
__device__ __forceinline__ float sig_acc(float x) { return 1.0f / (1.0f + __expf(-x)); }

__device__ __forceinline__ void st_h2(void* p, float a, float b) {
    *(__half2*)p = __floats2half2_rn(a, b);
}
__device__ __forceinline__ uint32_t h2u(float a, float b) {
    __half2 h = __floats2half2_rn(a, b);
    return *reinterpret_cast<uint32_t*>(&h);
}
__device__ __forceinline__ void unp(uint32_t u, float& a, float& b) {
    __half2 h = *reinterpret_cast<__half2*>(&u);
    float2 f = __half22float2(h);
    a = f.x; b = f.y;
}
__device__ __forceinline__ void unp8(uint4 q, float* v) {
    unp(q.x, v[0], v[1]); unp(q.y, v[2], v[3]);
    unp(q.z, v[4], v[5]); unp(q.w, v[6], v[7]);
}

// ---------------- LSTM kernel ----------------
extern "C" __global__ void __launch_bounds__(NTHR, 1)
lstm_kernel(const float* __restrict__ x,    // [2048][128][64]
            const float* __restrict__ Wih,  // [512][64]
            const float* __restrict__ Whh,  // [512][128]
            const float* __restrict__ bih,  // [512]
            const float* __restrict__ bhh)  // [512]
{
    extern __shared__ unsigned char smem[];
    const uint32_t sbase = smem_u32(smem);
    unsigned char* preP = smem + SM_PRE;

    const int tid  = threadIdx.x;
    const int lane = tid & 31;
    const int wid  = tid >> 5;      // 0..15
    const int gate = tid >> 7;      // 0=i 1=f 2=g 3=o
    const int j    = tid & 127;
    const int b0   = blockIdx.x * BT;

    // ---- stage W = [Wih | Whh] fp16, swizzled ----
    for (int i = tid; i < NG * Dn; i += NTHR) {
        int n = i >> 6, k = i & 63;
        *(__half*)(smem + SM_W + w_off(n, k)) = __float2half(Wih[i]);
    }
    for (int i = tid; i < NG * Hn; i += NTHR) {
        int n = i >> 7, k = 64 + (i & 127);
        *(__half*)(smem + SM_W + w_off(n, k)) = __float2half(Whh[i]);
    }
    // h_{-1} = 0
    for (int i = tid; i < BT * Hn; i += NTHR) {
        int b = i >> 7, jj = i & 127;
        *(__half*)(smem + SM_ACT + b_off(b, 64 + jj)) = __float2half(0.0f);
    }

    // ---- x staging: each thread owns 2 (b,d) slots ----
    const int pb0 = tid >> 6;            // 0..7
    const int pd  = tid & 63;
    const int pb1 = pb0 + 8;             // 8..15
    const uint32_t xo0 = b_off(pb0, pd);
    const uint32_t xo1 = b_off(pb1, pd);
    const float* xbA = x + ((size_t)(b0 + pb0) * Ln) * Dn + pd;
    const float* xbB = x + ((size_t)(b0 + pb1) * Ln) * Dn + pd;
    float px0 = xbA[0], px1 = xbB[0];
    *(__half*)(smem + SM_ACT + xo0) = __float2half(px0);
    *(__half*)(smem + SM_ACT + xo1) = __float2half(px1);

    const float bias = bih[tid] + bhh[tid];

    // ---- mma lane geometry ----
    const int r0 = wid * 32;             // this warp's 32 gate rows
    const int lr = lane & 7, lm = lane >> 3;
    // A (weights): lanes -> (row, k-half) per ldmatrix.x4 fragment convention
    const uint32_t a2  = (uint32_t)((lm >> 1) * 16);                   // k8*2 bytes
    const uint32_t ax  = (uint32_t)lr * 16;                            // (row&7)*16 swizzle mask
    const uint32_t awA = sbase + SM_W + (uint32_t)(r0 + (lm & 1) * 8 + lr) * 128;
    const uint32_t awB = awA + 16 * 128;                               // mt=1 tile (+16 rows)
    // B (acts): lanes -> (n row, k-half)
    const uint32_t b2  = (uint32_t)((lm & 1) * 16);
    const int      bn  = (lm >> 1) * 8 + lr;
    const uint32_t bx  = (uint32_t)(bn & 7) * 16;
    const uint32_t bw  = sbase + SM_ACT + (uint32_t)bn * 128;

    // C-fragment store geometry
    const uint32_t g8 = lane >> 2;       // row within 8
    const uint32_t t4 = (lane & 3) * 4;  // col-pair byte offset

    // ---- update-thread state (warpgroups 2,3) ----
    float cst[8], hsum[8];
    #pragma unroll
    for (int b = 0; b < 8; b++) { cst[b] = 0.0f; hsum[b] = 0.0f; }
    const int upd  = (gate >= 2);
    const int bsel = (gate == 2) ? 1 : 0;    // gate2 -> b8..15, gate3 -> b0..7
    const uint32_t hk      = (uint32_t)(64 + j);
    const uint32_t h_chunk = SM_ACT + (hk >> 6) * 2048;
    const uint32_t h_klo   = (hk & 63) * 2;

    __syncthreads();

    #pragma unroll 1
    for (int t = 0; t < Ln; t++) {
        if (t + 1 < Ln) { px0 = xbA[(t + 1) * Dn]; px1 = xbB[(t + 1) * Dn]; }

        // ---- GEMM: D[512,16] = W @ act, per-warp 32x16 tile ----
        float d00[4] = {0,0,0,0}, d01[4] = {0,0,0,0};
        float d10[4] = {0,0,0,0}, d11[4] = {0,0,0,0};
        #pragma unroll
        for (int kc = 0; kc < 12; kc++) {
            const uint32_t chW = (uint32_t)((kc * 16) >> 6) * 65536u;
            const uint32_t chB = (uint32_t)((kc * 16) >> 6) * 2048u;
            const uint32_t klo = (uint32_t)((kc * 16) & 63) * 2u;
            const uint32_t offA = (klo + a2) ^ ax;
            const uint32_t offB = (klo + b2) ^ bx;
            uint32_t af0[4], af1[4], bf[4];
            LDSM4(af0, awA + chW + offA);
            LDSM4(af1, awB + chW + offA);
            LDSM4(bf,  bw  + chB + offB);
            MMA4(d00, af0, bf[0], bf[1]);
            MMA4(d01, af0, bf[2], bf[3]);
            MMA4(d10, af1, bf[0], bf[1]);
            MMA4(d11, af1, bf[2], bf[3]);
        }
        // ---- store preacts fp16 to pre[512][16] (conflict-free, 48B rows) ----
        {
            unsigned char* p0 = preP + (uint32_t)(r0 + g8) * PRE_STR + t4;
            st_h2(p0,                     d00[0], d00[1]);
            st_h2(p0 + 8 * PRE_STR,       d00[2], d00[3]);
            st_h2(p0 + 16,                d01[0], d01[1]);
            st_h2(p0 + 16 + 8 * PRE_STR,  d01[2], d01[3]);
            unsigned char* p1 = p0 + 16 * PRE_STR;
            st_h2(p1,                     d10[0], d10[1]);
            st_h2(p1 + 8 * PRE_STR,       d10[2], d10[3]);
            st_h2(p1 + 16,                d11[0], d11[1]);
            st_h2(p1 + 16 + 8 * PRE_STR,  d11[2], d11[3]);
        }
        __syncthreads();   // S2: preacts visible; act-buffer reads complete

        // ---- phase A: activation of own gate row n=tid, in-place ----
        {
            uint4 q0 = *(const uint4*)(preP + (uint32_t)tid * PRE_STR);
            uint4 q1 = *(const uint4*)(preP + (uint32_t)tid * PRE_STR + 16);
            float v[16];
            unp8(q0, v); unp8(q1, v + 8);
            float w[16];
            if (gate == 0) {
                #pragma unroll
                for (int b = 0; b < 16; b++) w[b] = sig_fast(v[b] + bias);
            } else if (gate == 1) {
                #pragma unroll
                for (int b = 0; b < 16; b++) w[b] = sig_acc(v[b] + bias);
            } else if (gate == 2) {
                #pragma unroll
                for (int b = 0; b < 16; b++) w[b] = tanh_ap(v[b] + bias);
            } else {
                #pragma unroll
                for (int b = 0; b < 16; b++) w[b] = sig_fast(v[b] + bias);
            }
            uint4 o0, o1;
            o0.x = h2u(w[0],  w[1]);  o0.y = h2u(w[2],  w[3]);
            o0.z = h2u(w[4],  w[5]);  o0.w = h2u(w[6],  w[7]);
            o1.x = h2u(w[8],  w[9]);  o1.y = h2u(w[10], w[11]);
            o1.z = h2u(w[12], w[13]); o1.w = h2u(w[14], w[15]);
            *(uint4*)(preP + (uint32_t)tid * PRE_STR)      = o0;
            *(uint4*)(preP + (uint32_t)tid * PRE_STR + 16) = o1;
        }
        // stage x_{t+1} (act buffer free since S2)
        *(__half*)(smem + SM_ACT + xo0) = __float2half(px0);
        *(__half*)(smem + SM_ACT + xo1) = __float2half(px1);
        __syncthreads();   // S3: activated gates visible

        // ---- phase B: c/h update, split across warpgroups 2 & 3 ----
        if (upd) {
            const uint32_t ho = (uint32_t)(bsel * 16);
            uint4 qi = *(const uint4*)(preP + (uint32_t)(      j) * PRE_STR + ho);
            uint4 qf = *(const uint4*)(preP + (uint32_t)(128 + j) * PRE_STR + ho);
            uint4 qg = *(const uint4*)(preP + (uint32_t)(256 + j) * PRE_STR + ho);
            uint4 qo = *(const uint4*)(preP + (uint32_t)(384 + j) * PRE_STR + ho);
            float iv[8], fv[8], gv[8], ov[8];
            unp8(qi, iv); unp8(qf, fv); unp8(qg, gv); unp8(qo, ov);
            #pragma unroll
            for (int b = 0; b < 8; b++) {
                cst[b] = fmaf(fv[b], cst[b], iv[b] * gv[b]);
                float hv = ov[b] * tanh_ap(cst[b]);
                hsum[b] += hv;
                const uint32_t bb = (uint32_t)(bsel * 8 + b);
                *(__half*)(smem + h_chunk + bb * 128 + (h_klo ^ ((uint32_t)b * 16))) =
                    __float2half(hv);
            }
        }
        __syncthreads();   // S5: act buffer (x_{t+1}, h_t) complete
    }

    if (upd) {
        #pragma unroll
        for (int b = 0; b < 8; b++)
            g_rep[(size_t)(b0 + bsel * 8 + b) * Hn + j] = hsum[b];
    }
}

// ---------------- head: mean over cycles + classifier + log_softmax ----------------
extern "C" __global__ void head_kernel(const float* __restrict__ Wcls,  // [10][128]
                                       const float* __restrict__ bcls,  // [10]
                                       float* __restrict__ out)         // [64][10]
{
    __shared__ float gm[Hn];
    __shared__ float lg[NCLSn];
    const int g = blockIdx.x, tid = threadIdx.x;

    float s = 0.0f;
    for (int cc = 0; cc < Cn; cc++)
        s += g_rep[(size_t)(g * Cn + cc) * Hn + tid];
    gm[tid] = s * (1.0f / (float)Cn);
    __syncthreads();

    if (tid < NCLSn) {
        float a = bcls[tid];
        #pragma unroll 4
        for (int k = 0; k < Hn; k++) a += gm[k] * Wcls[tid * Hn + k];
        lg[tid] = a;
    }
    __syncthreads();

    if (tid == 0) {
        float m = lg[0];
        for (int i = 1; i < NCLSn; i++) m = fmaxf(m, lg[i]);
        float se = 0.0f;
        for (int i = 0; i < NCLSn; i++) se += expf(lg[i] - m);
        float lse = m + logf(se);
        for (int i = 0; i < NCLSn; i++) out[g * NCLSn + i] = lg[i] - lse;
    }
}

extern "C" void kernel_launch(void* const* d_in, const int* in_sizes, int n_in,
                              void* d_out, int out_size)
{
    const float* x    = (const float*)d_in[0];
    const float* Wih  = (const float*)d_in[1];
    const float* Whh  = (const float*)d_in[2];
    const float* bih  = (const float*)d_in[3];
    const float* bhh  = (const float*)d_in[4];
    const float* Wcls = (const float*)d_in[5];
    const float* bcls = (const float*)d_in[6];
    float* out = (float*)d_out;

    cudaFuncSetAttribute(lstm_kernel,
                         cudaFuncAttributeMaxDynamicSharedMemorySize, SM_TOTAL);

    lstm_kernel<<<NCTA, NTHR, SM_TOTAL>>>(x, Wih, Whh, bih, bhh);
    head_kernel<<<Gn, Hn>>>(Wcls, bcls, out);
}

// round 9
// speedup vs baseline: 8.4534x; 1.4408x over previous
#include <cuda_runtime.h>
#include <cuda_fp16.h>
#include <cstdint>
#include <math.h>

// ---------------- problem constants ----------------
#define Gn   64
#define Cn   32
#define Ln   128
#define Dn   64
#define Hn   128
#define NG   512          // 4*H gate rows
#define NCLSn 10
#define BT   16           // sequences per CTA
#define NBATCH (Gn*Cn)    // 2048
#define NCTA (NBATCH/BT)  // 128
#define NTHR 512

__device__ float g_rep[NBATCH * Hn];

// ---------------- smem layout (bytes) ----------------
// W   : fp16 [512 r][192 k], 3 chunks of [512][64], 128B rows, SW128 swizzle
// ACT : fp16 [16 b][192 k], 3 chunks of [16][64], 128B rows, SW128 swizzle
// PRE : fp16 [512 r][16 b], row stride 48B (padded)
#define SM_W     0                          // 3*512*128 = 196608
#define SM_ACT   196608                     // 3*16*128  = 6144
#define SM_PRE   (196608 + 6144)            // 512*48    = 24576
#define PRE_STR  48
#define SM_TOTAL (SM_PRE + NG*PRE_STR)      // 227328

// ---------------- helpers ----------------
__device__ __forceinline__ uint32_t smem_u32(const void* p) {
    uint32_t a;
    asm("{ .reg .u64 t; cvta.to.shared.u64 t, %1; cvt.u32.u64 %0, t; }" : "=r"(a) : "l"(p));
    return a;
}
__device__ __forceinline__ uint32_t swz(uint32_t o) { return o ^ ((o >> 3) & 0x70); }
__device__ __forceinline__ uint32_t w_off(int n, int k) {
    return (uint32_t)((k >> 6) * 65536) + swz((uint32_t)(n * 128 + (k & 63) * 2));
}
__device__ __forceinline__ uint32_t b_off(int b, int k) {
    return (uint32_t)((k >> 6) * 2048) + swz((uint32_t)(b * 128 + (k & 63) * 2));
}

#define LDSM4(R, A)                                                            \
    asm volatile("ldmatrix.sync.aligned.m8n8.x4.shared.b16 {%0,%1,%2,%3}, [%4];" \
        : "=r"((R)[0]), "=r"((R)[1]), "=r"((R)[2]), "=r"((R)[3]) : "r"(A))

#define MMA4(D, A, B0, B1)                                                     \
    asm volatile("mma.sync.aligned.m16n8k16.row.col.f32.f16.f16.f32 "          \
        "{%0,%1,%2,%3},{%4,%5,%6,%7},{%8,%9},{%0,%1,%2,%3};"                   \
        : "+f"((D)[0]), "+f"((D)[1]), "+f"((D)[2]), "+f"((D)[3])               \
        : "r"((A)[0]), "r"((A)[1]), "r"((A)[2]), "r"((A)[3]), "r"(B0), "r"(B1))

__device__ __forceinline__ float tanh_ap(float x) {
    float y; asm("tanh.approx.f32 %0, %1;" : "=f"(y) : "f"(x)); return y;
}
__device__ __forceinline__ float sig_fast(float x) { return fmaf(0.5f, tanh_ap(0.5f * x), 0.5f); }
__device__ __forceinline__ float sig_acc(float x) { return 1.0f / (1.0f + __expf(-x)); }

__device__ __forceinline__ void st_h2(void* p, float a, float b) {
    *(__half2*)p = __floats2half2_rn(a, b);
}
__device__ __forceinline__ void unp(uint32_t u, float& a, float& b) {
    __half2 h = *reinterpret_cast<__half2*>(&u);
    float2 f = __half22float2(h);
    a = f.x; b = f.y;
}

// ---------------- LSTM kernel ----------------
extern "C" __global__ void __launch_bounds__(NTHR, 1)
lstm_kernel(const float* __restrict__ x,    // [2048][128][64]
            const float* __restrict__ Wih,  // [512][64]
            const float* __restrict__ Whh,  // [512][128]
            const float* __restrict__ bih,  // [512]
            const float* __restrict__ bhh)  // [512]
{
    extern __shared__ unsigned char smem[];
    const uint32_t sbase = smem_u32(smem);
    unsigned char* preP = smem + SM_PRE;

    const int tid  = threadIdx.x;
    const int lane = tid & 31;
    const int wid  = tid >> 5;      // 0..15
    const int b0   = blockIdx.x * BT;

    // ---- stage W = [Wih | Whh] fp16, swizzled ----
    for (int i = tid; i < NG * Dn; i += NTHR) {
        int n = i >> 6, k = i & 63;
        *(__half*)(smem + SM_W + w_off(n, k)) = __float2half(Wih[i]);
    }
    for (int i = tid; i < NG * Hn; i += NTHR) {
        int n = i >> 7, k = 64 + (i & 127);
        *(__half*)(smem + SM_W + w_off(n, k)) = __float2half(Whh[i]);
    }
    // h_{-1} = 0
    for (int i = tid; i < BT * Hn; i += NTHR) {
        int b = i >> 7, jj = i & 127;
        *(__half*)(smem + SM_ACT + b_off(b, 64 + jj)) = __float2half(0.0f);
    }

    // ---- x staging: each thread owns 2 (b,d) slots ----
    const int pb0 = tid >> 6;            // 0..7
    const int pd  = tid & 63;
    const uint32_t xo0 = b_off(pb0, pd);
    const uint32_t xo1 = b_off(pb0 + 8, pd);
    const float* xbA = x + ((size_t)(b0 + pb0) * Ln) * Dn + pd;
    const float* xbB = x + ((size_t)(b0 + pb0 + 8) * Ln) * Dn + pd;
    float px0 = xbA[0], px1 = xbB[0];
    *(__half*)(smem + SM_ACT + xo0) = __float2half(px0);
    *(__half*)(smem + SM_ACT + xo1) = __float2half(px1);

    // ---- mma lane geometry (per-warp 32x16 tile of D[512,16]) ----
    const int r0 = wid * 32;
    const int lr = lane & 7, lm = lane >> 3;
    const uint32_t a2  = (uint32_t)((lm >> 1) * 16);
    const uint32_t ax  = (uint32_t)lr * 16;
    const uint32_t awA = sbase + SM_W + (uint32_t)(r0 + (lm & 1) * 8 + lr) * 128;
    const uint32_t awB = awA + 16 * 128;
    const uint32_t b2  = (uint32_t)((lm & 1) * 16);
    const int      bn  = (lm >> 1) * 8 + lr;
    const uint32_t bx  = (uint32_t)(bn & 7) * 16;
    const uint32_t bw  = sbase + SM_ACT + (uint32_t)bn * 128;

    // C-fragment store geometry
    const uint32_t g8 = lane >> 2;
    const uint32_t t4 = (lane & 3) * 4;

    // ---- update mapping: thread owns (j = tid>>2, b = 4*(tid&3) .. +3) ----
    const int uj  = tid >> 2;       // hidden index 0..127
    const int ub0 = (tid & 3) * 4;  // first batch index of the 4 owned
    float cst[4], hsum[4];
    #pragma unroll
    for (int q = 0; q < 4; q++) { cst[q] = 0.0f; hsum[q] = 0.0f; }
    float biasv[4];
    #pragma unroll
    for (int g = 0; g < 4; g++)
        biasv[g] = bih[g * Hn + uj] + bhh[g * Hn + uj];

    // h store: k = 64 + uj
    const uint32_t hk      = (uint32_t)(64 + uj);
    const uint32_t h_chunk = SM_ACT + (hk >> 6) * 2048;
    const uint32_t h_klo   = (hk & 63) * 2;

    // preact row base addresses for the 4 gates of column uj
    const uint32_t pr = (uint32_t)uj * PRE_STR + (uint32_t)(tid & 3) * 8;

    __syncthreads();

    #pragma unroll 1
    for (int t = 0; t < Ln; t++) {
        if (t + 1 < Ln) { px0 = xbA[(t + 1) * Dn]; px1 = xbB[(t + 1) * Dn]; }

        // ---- GEMM: D[512,16] = W @ act ----
        float d00[4] = {0,0,0,0}, d01[4] = {0,0,0,0};
        float d10[4] = {0,0,0,0}, d11[4] = {0,0,0,0};
        #pragma unroll
        for (int kc = 0; kc < 12; kc++) {
            const uint32_t chW = (uint32_t)((kc * 16) >> 6) * 65536u;
            const uint32_t chB = (uint32_t)((kc * 16) >> 6) * 2048u;
            const uint32_t klo = (uint32_t)((kc * 16) & 63) * 2u;
            const uint32_t offA = (klo + a2) ^ ax;
            const uint32_t offB = (klo + b2) ^ bx;
            uint32_t af0[4], af1[4], bf[4];
            LDSM4(af0, awA + chW + offA);
            LDSM4(af1, awB + chW + offA);
            LDSM4(bf,  bw  + chB + offB);
            MMA4(d00, af0, bf[0], bf[1]);
            MMA4(d01, af0, bf[2], bf[3]);
            MMA4(d10, af1, bf[0], bf[1]);
            MMA4(d11, af1, bf[2], bf[3]);
        }
        // ---- store raw preacts fp16 to PRE[512][16] ----
        {
            unsigned char* p0 = preP + (uint32_t)(r0 + g8) * PRE_STR + t4;
            st_h2(p0,                     d00[0], d00[1]);
            st_h2(p0 + 8 * PRE_STR,       d00[2], d00[3]);
            st_h2(p0 + 16,                d01[0], d01[1]);
            st_h2(p0 + 16 + 8 * PRE_STR,  d01[2], d01[3]);
            unsigned char* p1 = p0 + 16 * PRE_STR;
            st_h2(p1,                     d10[0], d10[1]);
            st_h2(p1 + 8 * PRE_STR,       d10[2], d10[3]);
            st_h2(p1 + 16,                d11[0], d11[1]);
            st_h2(p1 + 16 + 8 * PRE_STR,  d11[2], d11[3]);
        }
        __syncthreads();   // S2: preacts visible; act-tile LDSM reads drained

        // ---- fused update: every thread does 4 (j,b) cells ----
        {
            uint2 qi = *(const uint2*)(preP + 0 * 128 * PRE_STR + pr);
            uint2 qf = *(const uint2*)(preP + 1 * 128 * PRE_STR + pr);
            uint2 qg = *(const uint2*)(preP + 2 * 128 * PRE_STR + pr);
            uint2 qo = *(const uint2*)(preP + 3 * 128 * PRE_STR + pr);
            float iv[4], fv[4], gv[4], ov[4];
            unp(qi.x, iv[0], iv[1]); unp(qi.y, iv[2], iv[3]);
            unp(qf.x, fv[0], fv[1]); unp(qf.y, fv[2], fv[3]);
            unp(qg.x, gv[0], gv[1]); unp(qg.y, gv[2], gv[3]);
            unp(qo.x, ov[0], ov[1]); unp(qo.y, ov[2], ov[3]);
            #pragma unroll
            for (int q = 0; q < 4; q++) {
                float i_ = sig_fast(iv[q] + biasv[0]);
                float f_ = sig_acc (fv[q] + biasv[1]);
                float g_ = tanh_ap (gv[q] + biasv[2]);
                float o_ = sig_fast(ov[q] + biasv[3]);
                cst[q] = fmaf(f_, cst[q], i_ * g_);
                float hv = o_ * tanh_ap(cst[q]);
                hsum[q] += hv;
                const uint32_t b = (uint32_t)(ub0 + q);
                *(__half*)(smem + h_chunk + b * 128 + (h_klo ^ ((b & 7) * 16u))) =
                    __float2half(hv);
            }
        }
        // stage x_{t+1}
        if (t + 1 < Ln) {
            *(__half*)(smem + SM_ACT + xo0) = __float2half(px0);
            *(__half*)(smem + SM_ACT + xo1) = __float2half(px1);
        }
        __syncthreads();   // S5: act tile (x_{t+1}, h_t) complete
    }

    #pragma unroll
    for (int q = 0; q < 4; q++)
        g_rep[(size_t)(b0 + ub0 + q) * Hn + uj] = hsum[q];
}

// ---------------- head: mean over cycles + classifier + log_softmax ----------------
extern "C" __global__ void head_kernel(const float* __restrict__ Wcls,  // [10][128]
                                       const float* __restrict__ bcls,  // [10]
                                       float* __restrict__ out)         // [64][10]
{
    __shared__ float gm[Hn];
    __shared__ float lg[NCLSn];
    const int g = blockIdx.x, tid = threadIdx.x;

    float s = 0.0f;
    for (int cc = 0; cc < Cn; cc++)
        s += g_rep[(size_t)(g * Cn + cc) * Hn + tid];
    gm[tid] = s * (1.0f / (float)Cn);
    __syncthreads();

    if (tid < NCLSn) {
        float a = bcls[tid];
        #pragma unroll 4
        for (int k = 0; k < Hn; k++) a += gm[k] * Wcls[tid * Hn + k];
        lg[tid] = a;
    }
    __syncthreads();

    if (tid == 0) {
        float m = lg[0];
        for (int i = 1; i < NCLSn; i++) m = fmaxf(m, lg[i]);
        float se = 0.0f;
        for (int i = 0; i < NCLSn; i++) se += expf(lg[i] - m);
        float lse = m + logf(se);
        for (int i = 0; i < NCLSn; i++) out[g * NCLSn + i] = lg[i] - lse;
    }
}

extern "C" void kernel_launch(void* const* d_in, const int* in_sizes, int n_in,
                              void* d_out, int out_size)
{
    const float* x    = (const float*)d_in[0];
    const float* Wih  = (const float*)d_in[1];
    const float* Whh  = (const float*)d_in[2];
    const float* bih  = (const float*)d_in[3];
    const float* bhh  = (const float*)d_in[4];
    const float* Wcls = (const float*)d_in[5];
    const float* bcls = (const float*)d_in[6];
    float* out = (float*)d_out;

    cudaFuncSetAttribute(lstm_kernel,
                         cudaFuncAttributeMaxDynamicSharedMemorySize, SM_TOTAL);

    lstm_kernel<<<NCTA, NTHR, SM_TOTAL>>>(x, Wih, Whh, bih, bhh);
    head_kernel<<<Gn, Hn>>>(Wcls, bcls, out);
}

// round 12
// speedup vs baseline: 9.2488x; 1.0941x over previous
#include <cuda_runtime.h>
#include <cuda_fp16.h>
#include <cstdint>
#include <math.h>

// ---------------- problem constants ----------------
#define Gn   64
#define Cn   32
#define Ln   128
#define Dn   64
#define Hn   128
#define NG   512          // 4*H gate rows
#define NCLSn 10
#define BT   16           // sequences per CTA
#define NBATCH (Gn*Cn)    // 2048
#define NCTA (NBATCH/BT)  // 128
#define NTHR 512

__device__ float g_rep[NBATCH * Hn];

// ---------------- smem layout (bytes) ----------------
// W    : fp16 [512 r'][192 k], rows PERMUTED (see below), 3 chunks of [512][64],
//        128B rows, SW128 swizzle
// ACT0/1: fp16 [16 b][192 k], 3 chunks of [16][64], 128B rows, SW128 swizzle
#define SM_W     0                          // 3*512*128 = 196608
#define SM_ACT0  196608                     // 6144
#define SM_ACT1  (196608 + 6144)            // 6144
#define SM_TOTAL (SM_ACT1 + 6144)           // 208896

// ---------------- helpers ----------------
__device__ __forceinline__ uint32_t smem_u32(const void* p) {
    uint32_t a;
    asm("{ .reg .u64 t; cvta.to.shared.u64 t, %1; cvt.u32.u64 %0, t; }" : "=r"(a) : "l"(p));
    return a;
}
__device__ __forceinline__ uint32_t swz(uint32_t o) { return o ^ ((o >> 3) & 0x70); }
__device__ __forceinline__ uint32_t w_off(int n, int k) {
    return (uint32_t)((k >> 6) * 65536) + swz((uint32_t)(n * 128 + (k & 63) * 2));
}
__device__ __forceinline__ uint32_t b_off(int b, int k) {
    return (uint32_t)((k >> 6) * 2048) + swz((uint32_t)(b * 128 + (k & 63) * 2));
}
// W row permutation: original gate-row n = g*128 + j  ->  r' = 32*(j>>3) + 8*g + (j&7)
__device__ __forceinline__ int wperm(int g, int j) {
    return 32 * (j >> 3) + 8 * g + (j & 7);
}

#define LDSM4(R, A)                                                            \
    asm volatile("ldmatrix.sync.aligned.m8n8.x4.shared.b16 {%0,%1,%2,%3}, [%4];" \
        : "=r"((R)[0]), "=r"((R)[1]), "=r"((R)[2]), "=r"((R)[3]) : "r"(A))

#define MMA4(D, A, B0, B1)                                                     \
    asm volatile("mma.sync.aligned.m16n8k16.row.col.f32.f16.f16.f32 "          \
        "{%0,%1,%2,%3},{%4,%5,%6,%7},{%8,%9},{%0,%1,%2,%3};"                   \
        : "+f"((D)[0]), "+f"((D)[1]), "+f"((D)[2]), "+f"((D)[3])               \
        : "r"((A)[0]), "r"((A)[1]), "r"((A)[2]), "r"((A)[3]), "r"(B0), "r"(B1))

__device__ __forceinline__ __half2 tanh_h2(__half2 x) {
    uint32_t u = *reinterpret_cast<uint32_t*>(&x), y;
    asm("tanh.approx.f16x2 %0, %1;" : "=r"(y) : "r"(u));
    return *reinterpret_cast<__half2*>(&y);
}
// sigmoid(a),sigmoid(b) in half2: 0.5*tanh(0.5x)+0.5
__device__ __forceinline__ __half2 sig_h2(float a, float b) {
    __half2 t = tanh_h2(__floats2half2_rn(0.5f * a, 0.5f * b));
    return __hfma2(t, __float2half2_rn(0.5f), __float2half2_rn(0.5f));
}

// ---------------- LSTM kernel ----------------
extern "C" __global__ void __launch_bounds__(NTHR, 1)
lstm_kernel(const float* __restrict__ x,    // [2048][128][64]
            const float* __restrict__ Wih,  // [512][64]
            const float* __restrict__ Whh,  // [512][128]
            const float* __restrict__ bih,  // [512]
            const float* __restrict__ bhh)  // [512]
{
    extern __shared__ unsigned char smem[];
    const uint32_t sbase = smem_u32(smem);

    const int tid  = threadIdx.x;
    const int lane = tid & 31;
    const int wid  = tid >> 5;      // 0..15
    const int b0   = blockIdx.x * BT;

    // ---- stage W (row-permuted) fp16, swizzled ----
    for (int i = tid; i < NG * Dn; i += NTHR) {
        int n = i >> 6, k = i & 63;
        int rp = wperm(n >> 7, n & 127);
        *(__half*)(smem + SM_W + w_off(rp, k)) = __float2half(Wih[i]);
    }
    for (int i = tid; i < NG * Hn; i += NTHR) {
        int n = i >> 7, k = 64 + (i & 127);
        int rp = wperm(n >> 7, n & 127);
        *(__half*)(smem + SM_W + w_off(rp, k)) = __float2half(Whh[i]);
    }
    // h_{-1} = 0 in ACT0
    for (int i = tid; i < BT * Hn; i += NTHR) {
        int b = i >> 7, jj = i & 127;
        *(__half*)(smem + SM_ACT0 + b_off(b, 64 + jj)) = __float2half(0.0f);
    }

    // ---- x staging: each thread owns 2 (b,d) slots ----
    const int pb0 = tid >> 6;            // 0..7
    const int pd  = tid & 63;
    const uint32_t xo0 = b_off(pb0, pd);
    const uint32_t xo1 = b_off(pb0 + 8, pd);
    const float* xbA = x + ((size_t)(b0 + pb0) * Ln) * Dn + pd;
    const float* xbB = x + ((size_t)(b0 + pb0 + 8) * Ln) * Dn + pd;
    float px0 = xbA[0], px1 = xbB[0];
    *(__half*)(smem + SM_ACT0 + xo0) = __float2half(px0);
    *(__half*)(smem + SM_ACT0 + xo1) = __float2half(px1);

    // ---- mma lane geometry (per-warp 32x16 tile, permuted rows) ----
    const int r0 = wid * 32;
    const int lr = lane & 7, lm = lane >> 3;
    const uint32_t a2  = (uint32_t)((lm >> 1) * 16);
    const uint32_t ax  = (uint32_t)lr * 16;
    const uint32_t awA = sbase + SM_W + (uint32_t)(r0 + (lm & 1) * 8 + lr) * 128;
    const uint32_t awB = awA + 16 * 128;
    const uint32_t b2  = (uint32_t)((lm & 1) * 16);
    const int      bn  = (lm >> 1) * 8 + lr;
    const uint32_t bx  = (uint32_t)(bn & 7) * 16;
    const uint32_t bw0 = sbase + SM_ACT0 + (uint32_t)bn * 128;
    const uint32_t bw1 = sbase + SM_ACT1 + (uint32_t)bn * 128;

    // ---- per-lane update geometry ----
    // lane owns j = 8*wid + (lane>>2); batches bA=2t,2t+1 and bB=8+2t,9+2t (t=lane&3)
    const int jl = 8 * wid + (lane >> 2);
    const int tt = lane & 3;
    const int bA = 2 * tt, bB = 8 + 2 * tt;
    const float bI = bih[      jl] + bhh[      jl];
    const float bF = bih[128 + jl] + bhh[128 + jl];
    const float bG = bih[256 + jl] + bhh[256 + jl];
    const float bO = bih[384 + jl] + bhh[384 + jl];

    // h store address pieces: k = 64 + jl
    const uint32_t h_chunk = (uint32_t)((64 + jl) >> 6) * 2048u;
    const uint32_t h_klo   = (uint32_t)((64 + jl) & 63) * 2u;
    const uint32_t hoffA0 = h_chunk + (uint32_t)bA * 128u + (h_klo ^ (((uint32_t)bA & 7) * 16u));
    const uint32_t hoffA1 = h_chunk + (uint32_t)(bA + 1) * 128u + (h_klo ^ (((uint32_t)(bA + 1) & 7) * 16u));
    const uint32_t hoffB0 = h_chunk + (uint32_t)bB * 128u + (h_klo ^ (((uint32_t)bB & 7) * 16u));
    const uint32_t hoffB1 = h_chunk + (uint32_t)(bB + 1) * 128u + (h_klo ^ (((uint32_t)(bB + 1) & 7) * 16u));

    float c0 = 0.0f, c1 = 0.0f, c2 = 0.0f, c3 = 0.0f;
    float hs0 = 0.0f, hs1 = 0.0f, hs2 = 0.0f, hs3 = 0.0f;

    __syncthreads();

    #pragma unroll 1
    for (int t = 0; t < Ln; t++) {
        const uint32_t bwC   = (t & 1) ? bw1 : bw0;               // GEMM reads
        unsigned char* anext = smem + ((t & 1) ? SM_ACT0 : SM_ACT1); // update writes

        if (t + 1 < Ln) { px0 = xbA[(t + 1) * Dn]; px1 = xbB[(t + 1) * Dn]; }

        // ---- GEMM: D[512,16] = W' @ act ----
        float d00[4] = {0,0,0,0}, d01[4] = {0,0,0,0};
        float d10[4] = {0,0,0,0}, d11[4] = {0,0,0,0};
        #pragma unroll
        for (int kc = 0; kc < 12; kc++) {
            const uint32_t chW = (uint32_t)((kc * 16) >> 6) * 65536u;
            const uint32_t chB = (uint32_t)((kc * 16) >> 6) * 2048u;
            const uint32_t klo = (uint32_t)((kc * 16) & 63) * 2u;
            const uint32_t offA = (klo + a2) ^ ax;
            const uint32_t offB = (klo + b2) ^ bx;
            uint32_t af0[4], af1[4], bf[4];
            LDSM4(af0, awA + chW + offA);
            LDSM4(af1, awB + chW + offA);
            LDSM4(bf,  bwC + chB + offB);
            MMA4(d00, af0, bf[0], bf[1]);
            MMA4(d01, af0, bf[2], bf[3]);
            MMA4(d10, af1, bf[0], bf[1]);
            MMA4(d11, af1, bf[2], bf[3]);
        }

        // ---- in-register update ----
        // pair A (b = bA, bA+1): i=d00[0,1] f=d00[2,3] g=d10[0,1] o=d10[2,3]
        {
            __half2 si = sig_h2(d00[0] + bI, d00[1] + bI);
            __half2 sf = sig_h2(d00[2] + bF, d00[3] + bF);
            __half2 tg = tanh_h2(__floats2half2_rn(d10[0] + bG, d10[1] + bG));
            __half2 so = sig_h2(d10[2] + bO, d10[3] + bO);
            float2 ig = __half22float2(__hmul2(si, tg));
            float2 ff = __half22float2(sf);
            c0 = fmaf(ff.x, c0, ig.x);
            c1 = fmaf(ff.y, c1, ig.y);
            __half2 hh = __hmul2(so, tanh_h2(__floats2half2_rn(c0, c1)));
            float2 hf = __half22float2(hh);
            hs0 += hf.x; hs1 += hf.y;
            *(__half*)(anext + hoffA0) = __low2half(hh);
            *(__half*)(anext + hoffA1) = __high2half(hh);
        }
        // pair B (b = bB, bB+1): i=d01[0,1] f=d01[2,3] g=d11[0,1] o=d11[2,3]
        {
            __half2 si = sig_h2(d01[0] + bI, d01[1] + bI);
            __half2 sf = sig_h2(d01[2] + bF, d01[3] + bF);
            __half2 tg = tanh_h2(__floats2half2_rn(d11[0] + bG, d11[1] + bG));
            __half2 so = sig_h2(d11[2] + bO, d11[3] + bO);
            float2 ig = __half22float2(__hmul2(si, tg));
            float2 ff = __half22float2(sf);
            c2 = fmaf(ff.x, c2, ig.x);
            c3 = fmaf(ff.y, c3, ig.y);
            __half2 hh = __hmul2(so, tanh_h2(__floats2half2_rn(c2, c3)));
            float2 hf = __half22float2(hh);
            hs2 += hf.x; hs3 += hf.y;
            *(__half*)(anext + hoffB0) = __low2half(hh);
            *(__half*)(anext + hoffB1) = __high2half(hh);
        }

        // stage x_{t+1}
        if (t + 1 < Ln) {
            *(__half*)(anext + xo0) = __float2half(px0);
            *(__half*)(anext + xo1) = __float2half(px1);
        }
        __syncthreads();   // next act tile (x_{t+1}, h_t) complete
    }

    g_rep[(size_t)(b0 + bA)     * Hn + jl] = hs0;
    g_rep[(size_t)(b0 + bA + 1) * Hn + jl] = hs1;
    g_rep[(size_t)(b0 + bB)     * Hn + jl] = hs2;
    g_rep[(size_t)(b0 + bB + 1) * Hn + jl] = hs3;
}

// ---------------- head: mean over cycles + classifier + log_softmax ----------------
extern "C" __global__ void head_kernel(const float* __restrict__ Wcls,  // [10][128]
                                       const float* __restrict__ bcls,  // [10]
                                       float* __restrict__ out)         // [64][10]
{
    __shared__ float gm[Hn];
    __shared__ float lg[NCLSn];
    const int g = blockIdx.x, tid = threadIdx.x;

    float s = 0.0f;
    for (int cc = 0; cc < Cn; cc++)
        s += g_rep[(size_t)(g * Cn + cc) * Hn + tid];
    gm[tid] = s * (1.0f / (float)Cn);
    __syncthreads();

    if (tid < NCLSn) {
        float a = bcls[tid];
        #pragma unroll 4
        for (int k = 0; k < Hn; k++) a += gm[k] * Wcls[tid * Hn + k];
        lg[tid] = a;
    }
    __syncthreads();

    if (tid == 0) {
        float m = lg[0];
        for (int i = 1; i < NCLSn; i++) m = fmaxf(m, lg[i]);
        float se = 0.0f;
        for (int i = 0; i < NCLSn; i++) se += expf(lg[i] - m);
        float lse = m + logf(se);
        for (int i = 0; i < NCLSn; i++) out[g * NCLSn + i] = lg[i] - lse;
    }
}

extern "C" void kernel_launch(void* const* d_in, const int* in_sizes, int n_in,
                              void* d_out, int out_size)
{
    const float* x    = (const float*)d_in[0];
    const float* Wih  = (const float*)d_in[1];
    const float* Whh  = (const float*)d_in[2];
    const float* bih  = (const float*)d_in[3];
    const float* bhh  = (const float*)d_in[4];
    const float* Wcls = (const float*)d_in[5];
    const float* bcls = (const float*)d_in[6];
    float* out = (float*)d_out;

    cudaFuncSetAttribute(lstm_kernel,
                         cudaFuncAttributeMaxDynamicSharedMemorySize, SM_TOTAL);

    lstm_kernel<<<NCTA, NTHR, SM_TOTAL>>>(x, Wih, Whh, bih, bhh);
    head_kernel<<<Gn, Hn>>>(Wcls, bcls, out);
}

// round 13
// speedup vs baseline: 12.2546x; 1.3250x over previous
#include <cuda_runtime.h>
#include <cuda_fp16.h>
#include <cstdint>
#include <math.h>

// ---------------- problem constants ----------------
#define Gn   64
#define Cn   32
#define Ln   128
#define Dn   64
#define Hn   128
#define NG   512          // 4*H gate rows
#define NCLSn 10
#define BT   16           // sequences per CTA
#define NBATCH (Gn*Cn)    // 2048
#define NCTA (NBATCH/BT)  // 128
#define NTHR 512

__device__ float g_rep[NBATCH * Hn];

// ---------------- smem layout (bytes) ----------------
// W    : fp16 [512 r'][192 k], rows PERMUTED, 3 chunks of [512][64], 128B rows, SW128
// ACT0/1: fp16 [16 b][192 k], 3 chunks of [16][64], 128B rows, SW128
#define SM_W     0                          // 196608
#define SM_ACT0  196608                     // 6144
#define SM_ACT1  (196608 + 6144)            // 6144
#define SM_TOTAL (SM_ACT1 + 6144)           // 208896

// ---------------- helpers ----------------
__device__ __forceinline__ uint32_t smem_u32(const void* p) {
    uint32_t a;
    asm("{ .reg .u64 t; cvta.to.shared.u64 t, %1; cvt.u32.u64 %0, t; }" : "=r"(a) : "l"(p));
    return a;
}
__device__ __forceinline__ uint32_t swz(uint32_t o) { return o ^ ((o >> 3) & 0x70); }
__device__ __forceinline__ uint32_t w_off(int n, int k) {
    return (uint32_t)((k >> 6) * 65536) + swz((uint32_t)(n * 128 + (k & 63) * 2));
}
__device__ __forceinline__ uint32_t b_off(int b, int k) {
    return (uint32_t)((k >> 6) * 2048) + swz((uint32_t)(b * 128 + (k & 63) * 2));
}
// W row permutation: gate-row n = g*128 + j  ->  r' = 32*(j>>3) + 8*g + (j&7)
__device__ __forceinline__ int wperm(int g, int j) {
    return 32 * (j >> 3) + 8 * g + (j & 7);
}

#define LDSM4(R, A)                                                            \
    asm volatile("ldmatrix.sync.aligned.m8n8.x4.shared.b16 {%0,%1,%2,%3}, [%4];" \
        : "=r"((R)[0]), "=r"((R)[1]), "=r"((R)[2]), "=r"((R)[3]) : "r"(A))

// f16-accumulator MMA: C/D = 2 b32 regs (4 halves)
#define MMA4H(C0, C1, A, B0, B1)                                               \
    asm volatile("mma.sync.aligned.m16n8k16.row.col.f16.f16.f16.f16 "          \
        "{%0,%1},{%2,%3,%4,%5},{%6,%7},{%0,%1};"                               \
        : "+r"(C0), "+r"(C1)                                                   \
        : "r"((A)[0]), "r"((A)[1]), "r"((A)[2]), "r"((A)[3]), "r"(B0), "r"(B1))

__device__ __forceinline__ __half2 u2h(uint32_t u) { return *reinterpret_cast<__half2*>(&u); }
__device__ __forceinline__ __half2 tanh_h2(__half2 x) {
    uint32_t u = *reinterpret_cast<uint32_t*>(&x), y;
    asm("tanh.approx.f16x2 %0, %1;" : "=r"(y) : "r"(u));
    return *reinterpret_cast<__half2*>(&y);
}
__device__ __forceinline__ __half2 sig_h2p(__half2 x) {  // sigmoid of packed half2
    const __half2 h05 = __float2half2_rn(0.5f);
    return __hfma2(tanh_h2(__hmul2(x, h05)), h05, h05);
}
__device__ __forceinline__ uint32_t packh2(float a, float b) {
    __half2 h = __floats2half2_rn(a, b);
    return *reinterpret_cast<uint32_t*>(&h);
}

// ---------------- LSTM kernel ----------------
extern "C" __global__ void __launch_bounds__(NTHR, 1)
lstm_kernel(const float* __restrict__ x,    // [2048][128][64]
            const float* __restrict__ Wih,  // [512][64]
            const float* __restrict__ Whh,  // [512][128]
            const float* __restrict__ bih,  // [512]
            const float* __restrict__ bhh)  // [512]
{
    extern __shared__ unsigned char smem[];
    const uint32_t sbase = smem_u32(smem);

    const int tid  = threadIdx.x;
    const int lane = tid & 31;
    const int wid  = tid >> 5;      // 0..15
    const int b0   = blockIdx.x * BT;

    // ---- stage W (row-permuted) fp16, swizzled ----
    for (int i = tid; i < NG * Dn; i += NTHR) {
        int n = i >> 6, k = i & 63;
        int rp = wperm(n >> 7, n & 127);
        *(__half*)(smem + SM_W + w_off(rp, k)) = __float2half(Wih[i]);
    }
    for (int i = tid; i < NG * Hn; i += NTHR) {
        int n = i >> 7, k = 64 + (i & 127);
        int rp = wperm(n >> 7, n & 127);
        *(__half*)(smem + SM_W + w_off(rp, k)) = __float2half(Whh[i]);
    }
    // h_{-1} = 0 in ACT0
    for (int i = tid; i < BT * Hn; i += NTHR) {
        int b = i >> 7, jj = i & 127;
        *(__half*)(smem + SM_ACT0 + b_off(b, 64 + jj)) = __float2half(0.0f);
    }

    // ---- x staging: each thread owns 2 (b,d) slots ----
    const int pb0 = tid >> 6;            // 0..7
    const int pd  = tid & 63;
    const uint32_t xo0 = b_off(pb0, pd);
    const uint32_t xo1 = b_off(pb0 + 8, pd);
    const float* xbA = x + ((size_t)(b0 + pb0) * Ln) * Dn + pd;
    const float* xbB = x + ((size_t)(b0 + pb0 + 8) * Ln) * Dn + pd;
    float px0 = xbA[0], px1 = xbB[0];
    *(__half*)(smem + SM_ACT0 + xo0) = __float2half(px0);
    *(__half*)(smem + SM_ACT0 + xo1) = __float2half(px1);

    // ---- mma lane geometry ----
    const int r0 = wid * 32;
    const int lr = lane & 7, lm = lane >> 3;
    const uint32_t a2  = (uint32_t)((lm >> 1) * 16);
    const uint32_t ax  = (uint32_t)lr * 16;
    const uint32_t awA = sbase + SM_W + (uint32_t)(r0 + (lm & 1) * 8 + lr) * 128;
    const uint32_t awB = awA + 16 * 128;
    const uint32_t b2  = (uint32_t)((lm & 1) * 16);
    const int      bn  = (lm >> 1) * 8 + lr;
    const uint32_t bx  = (uint32_t)(bn & 7) * 16;
    const uint32_t bw0 = sbase + SM_ACT0 + (uint32_t)bn * 128;
    const uint32_t bw1 = sbase + SM_ACT1 + (uint32_t)bn * 128;

    // ---- per-lane update geometry ----
    const int jl = 8 * wid + (lane >> 2);
    const int tt = lane & 3;
    const int bA = 2 * tt, bB = 8 + 2 * tt;
    // packed gate biases for C-operand init
    const uint32_t uBI = packh2(bih[      jl] + bhh[      jl], bih[      jl] + bhh[      jl]);
    const uint32_t uBF = packh2(bih[128 + jl] + bhh[128 + jl], bih[128 + jl] + bhh[128 + jl]);
    const uint32_t uBG = packh2(bih[256 + jl] + bhh[256 + jl], bih[256 + jl] + bhh[256 + jl]);
    const uint32_t uBO = packh2(bih[384 + jl] + bhh[384 + jl], bih[384 + jl] + bhh[384 + jl]);

    // h store offsets: k = 64 + jl
    const uint32_t h_chunk = (uint32_t)((64 + jl) >> 6) * 2048u;
    const uint32_t h_klo   = (uint32_t)((64 + jl) & 63) * 2u;
    const uint32_t hoffA0 = h_chunk + (uint32_t)bA * 128u + (h_klo ^ (((uint32_t)bA & 7) * 16u));
    const uint32_t hoffA1 = h_chunk + (uint32_t)(bA + 1) * 128u + (h_klo ^ (((uint32_t)(bA + 1) & 7) * 16u));
    const uint32_t hoffB0 = h_chunk + (uint32_t)bB * 128u + (h_klo ^ (((uint32_t)bB & 7) * 16u));
    const uint32_t hoffB1 = h_chunk + (uint32_t)(bB + 1) * 128u + (h_klo ^ (((uint32_t)(bB + 1) & 7) * 16u));

    float c0 = 0.0f, c1 = 0.0f, c2 = 0.0f, c3 = 0.0f;
    float hs0 = 0.0f, hs1 = 0.0f, hs2 = 0.0f, hs3 = 0.0f;

    __syncthreads();

    // ---- cache W_hh fragments in registers (k = 64..191, 8 chunks) ----
    uint32_t wh0[8][4], wh1[8][4];
    #pragma unroll
    for (int kc = 0; kc < 8; kc++) {
        const int k = 64 + kc * 16;
        const uint32_t chW = (uint32_t)(k >> 6) * 65536u;
        const uint32_t klo = (uint32_t)((k & 63) * 2);
        const uint32_t off = (klo + a2) ^ ax;
        LDSM4(wh0[kc], awA + chW + off);
        LDSM4(wh1[kc], awB + chW + off);
    }

    #pragma unroll 1
    for (int t = 0; t < Ln; t++) {
        const uint32_t bwC   = (t & 1) ? bw1 : bw0;
        unsigned char* anext = smem + ((t & 1) ? SM_ACT0 : SM_ACT1);

        if (t + 1 < Ln) { px0 = xbA[(t + 1) * Dn]; px1 = xbB[(t + 1) * Dn]; }

        // accumulators (f16x2), preloaded with biases
        uint32_t a00c0 = uBI, a00c1 = uBF, a01c0 = uBI, a01c1 = uBF;
        uint32_t a10c0 = uBG, a10c1 = uBO, a11c0 = uBG, a11c1 = uBO;

        // ---- x-part: k = 0..63 (chunk 0), W_ih via LDSM ----
        #pragma unroll
        for (int kc = 0; kc < 4; kc++) {
            const uint32_t klo = (uint32_t)(kc * 32);
            const uint32_t offA = (klo + a2) ^ ax;
            const uint32_t offB = (klo + b2) ^ bx;
            uint32_t af0[4], af1[4], bf[4];
            LDSM4(af0, awA + offA);
            LDSM4(af1, awB + offA);
            LDSM4(bf,  bwC + offB);
            MMA4H(a00c0, a00c1, af0, bf[0], bf[1]);
            MMA4H(a01c0, a01c1, af0, bf[2], bf[3]);
            MMA4H(a10c0, a10c1, af1, bf[0], bf[1]);
            MMA4H(a11c0, a11c1, af1, bf[2], bf[3]);
        }
        // ---- h-part: k = 64..191, W_hh cached ----
        #pragma unroll
        for (int kc = 0; kc < 8; kc++) {
            const int k = 64 + kc * 16;
            const uint32_t chB = (uint32_t)(k >> 6) * 2048u;
            const uint32_t klo = (uint32_t)((k & 63) * 2);
            const uint32_t offB = (klo + b2) ^ bx;
            uint32_t bf[4];
            LDSM4(bf, bwC + chB + offB);
            MMA4H(a00c0, a00c1, wh0[kc], bf[0], bf[1]);
            MMA4H(a01c0, a01c1, wh0[kc], bf[2], bf[3]);
            MMA4H(a10c0, a10c1, wh1[kc], bf[0], bf[1]);
            MMA4H(a11c0, a11c1, wh1[kc], bf[2], bf[3]);
        }

        // ---- in-register update (native half2) ----
        {   // pair A: i=a00c0 f=a00c1 g=a10c0 o=a10c1
            __half2 si = sig_h2p(u2h(a00c0));
            __half2 sf = sig_h2p(u2h(a00c1));
            __half2 tg = tanh_h2(u2h(a10c0));
            __half2 so = sig_h2p(u2h(a10c1));
            float2 ig = __half22float2(__hmul2(si, tg));
            float2 ff = __half22float2(sf);
            c0 = fmaf(ff.x, c0, ig.x);
            c1 = fmaf(ff.y, c1, ig.y);
            __half2 hh = __hmul2(so, tanh_h2(__floats2half2_rn(c0, c1)));
            float2 hf = __half22float2(hh);
            hs0 += hf.x; hs1 += hf.y;
            *(__half*)(anext + hoffA0) = __low2half(hh);
            *(__half*)(anext + hoffA1) = __high2half(hh);
        }
        {   // pair B: i=a01c0 f=a01c1 g=a11c0 o=a11c1
            __half2 si = sig_h2p(u2h(a01c0));
            __half2 sf = sig_h2p(u2h(a01c1));
            __half2 tg = tanh_h2(u2h(a11c0));
            __half2 so = sig_h2p(u2h(a11c1));
            float2 ig = __half22float2(__hmul2(si, tg));
            float2 ff = __half22float2(sf);
            c2 = fmaf(ff.x, c2, ig.x);
            c3 = fmaf(ff.y, c3, ig.y);
            __half2 hh = __hmul2(so, tanh_h2(__floats2half2_rn(c2, c3)));
            float2 hf = __half22float2(hh);
            hs2 += hf.x; hs3 += hf.y;
            *(__half*)(anext + hoffB0) = __low2half(hh);
            *(__half*)(anext + hoffB1) = __high2half(hh);
        }

        // stage x_{t+1}
        if (t + 1 < Ln) {
            *(__half*)(anext + xo0) = __float2half(px0);
            *(__half*)(anext + xo1) = __float2half(px1);
        }
        __syncthreads();   // next act tile (x_{t+1}, h_t) complete
    }

    g_rep[(size_t)(b0 + bA)     * Hn + jl] = hs0;
    g_rep[(size_t)(b0 + bA + 1) * Hn + jl] = hs1;
    g_rep[(size_t)(b0 + bB)     * Hn + jl] = hs2;
    g_rep[(size_t)(b0 + bB + 1) * Hn + jl] = hs3;
}

// ---------------- head: mean over cycles + classifier + log_softmax ----------------
extern "C" __global__ void head_kernel(const float* __restrict__ Wcls,  // [10][128]
                                       const float* __restrict__ bcls,  // [10]
                                       float* __restrict__ out)         // [64][10]
{
    __shared__ float gm[Hn];
    __shared__ float lg[NCLSn];
    const int g = blockIdx.x, tid = threadIdx.x;

    float s = 0.0f;
    for (int cc = 0; cc < Cn; cc++)
        s += g_rep[(size_t)(g * Cn + cc) * Hn + tid];
    gm[tid] = s * (1.0f / (float)Cn);
    __syncthreads();

    if (tid < NCLSn) {
        float a = bcls[tid];
        #pragma unroll 4
        for (int k = 0; k < Hn; k++) a += gm[k] * Wcls[tid * Hn + k];
        lg[tid] = a;
    }
    __syncthreads();

    if (tid == 0) {
        float m = lg[0];
        for (int i = 1; i < NCLSn; i++) m = fmaxf(m, lg[i]);
        float se = 0.0f;
        for (int i = 0; i < NCLSn; i++) se += expf(lg[i] - m);
        float lse = m + logf(se);
        for (int i = 0; i < NCLSn; i++) out[g * NCLSn + i] = lg[i] - lse;
    }
}

extern "C" void kernel_launch(void* const* d_in, const int* in_sizes, int n_in,
                              void* d_out, int out_size)
{
    const float* x    = (const float*)d_in[0];
    const float* Wih  = (const float*)d_in[1];
    const float* Whh  = (const float*)d_in[2];
    const float* bih  = (const float*)d_in[3];
    const float* bhh  = (const float*)d_in[4];
    const float* Wcls = (const float*)d_in[5];
    const float* bcls = (const float*)d_in[6];
    float* out = (float*)d_out;

    cudaFuncSetAttribute(lstm_kernel,
                         cudaFuncAttributeMaxDynamicSharedMemorySize, SM_TOTAL);

    lstm_kernel<<<NCTA, NTHR, SM_TOTAL>>>(x, Wih, Whh, bih, bhh);
    head_kernel<<<Gn, Hn>>>(Wcls, bcls, out);
}